// round 1
// baseline (speedup 1.0000x reference)
#include <cuda_runtime.h>

// Problem geometry
#define NB   2
#define NI   256
#define NJ   256
#define NK   64
#define CVOL (NI*NJ*NK)            // 4,194,304 per (batch,channel)
#define NPIX ((long)NB*CVOL)       // 8,388,608 elements per channel over batch
#define NCELL ((double)NB*255.0*255.0*63.0)  // 8,193,150 cells

static __device__ double g_acc[4];   // [0]=b_xy  [1]=b_z  [2]=parallel  [3]=div

__global__ void init_acc_kernel() {
    if (threadIdx.x < 4) g_acc[threadIdx.x] = 0.0;
}

__global__ void __launch_bounds__(256)
loss_kernel(const float* __restrict__ O, const float* __restrict__ T)
{
    const int tid  = blockIdx.x * 256 + threadIdx.x;
    const int lane = tid & 31;
    const int row  = tid >> 5;            // 131072 rows = 2*256*256, exact cover
    const int b    = row >> 16;
    const int ij   = row & 65535;
    const int i    = ij >> 8;
    const int j    = ij & 255;

    const long base = (long)(i * NJ + j) * NK + 2 * lane;  // k = 2*lane
    const float* __restrict__ Ob = O + (long)b * 3 * CVOL;
    const float* __restrict__ Tb = T + (long)b * 4 * CVOL;

    // clamped corner offsets (loads stay in-bounds; contribution gated below)
    const int io = (i < NI - 1) ? (NJ * NK) : 0;
    const int jo = (j < NJ - 1) ? NK : 0;

    // ---- loads: 19 x LDG.64 per thread ----
    const float2 BX00 = *(const float2*)(Ob + base);
    const float2 BX10 = *(const float2*)(Ob + base + io);
    const float2 BX01 = *(const float2*)(Ob + base + jo);
    const float2 BX11 = *(const float2*)(Ob + base + io + jo);

    const float2 BY00 = *(const float2*)(Ob + CVOL + base);
    const float2 BY10 = *(const float2*)(Ob + CVOL + base + io);
    const float2 BY01 = *(const float2*)(Ob + CVOL + base + jo);
    const float2 BY11 = *(const float2*)(Ob + CVOL + base + io + jo);

    const float2 BZ00 = *(const float2*)(Ob + 2L*CVOL + base);
    const float2 BZ10 = *(const float2*)(Ob + 2L*CVOL + base + io);
    const float2 BZ01 = *(const float2*)(Ob + 2L*CVOL + base + jo);
    const float2 BZ11 = *(const float2*)(Ob + 2L*CVOL + base + io + jo);

    const float2 Z00  = *(const float2*)(Tb + 3L*CVOL + base);
    const float2 Z10  = *(const float2*)(Tb + 3L*CVOL + base + io);
    const float2 Z01  = *(const float2*)(Tb + 3L*CVOL + base + jo);
    const float2 Z11  = *(const float2*)(Tb + 3L*CVOL + base + io + jo);

    const float2 TX   = *(const float2*)(Tb + base);
    const float2 TY   = *(const float2*)(Tb + CVOL + base);
    const float2 TZ   = *(const float2*)(Tb + 2L*CVOL + base);

    // ---- warp-internal k+2 halo (lane l+1 holds k = 2l+2 in .x) ----
    const unsigned FULL = 0xffffffffu;
    const float nbx00 = __shfl_down_sync(FULL, BX00.x, 1);
    const float nbx10 = __shfl_down_sync(FULL, BX10.x, 1);
    const float nbx01 = __shfl_down_sync(FULL, BX01.x, 1);
    const float nbx11 = __shfl_down_sync(FULL, BX11.x, 1);
    const float nby00 = __shfl_down_sync(FULL, BY00.x, 1);
    const float nby10 = __shfl_down_sync(FULL, BY10.x, 1);
    const float nby01 = __shfl_down_sync(FULL, BY01.x, 1);
    const float nby11 = __shfl_down_sync(FULL, BY11.x, 1);
    const float nbz00 = __shfl_down_sync(FULL, BZ00.x, 1);
    const float nbz10 = __shfl_down_sync(FULL, BZ10.x, 1);
    const float nbz01 = __shfl_down_sync(FULL, BZ01.x, 1);
    const float nbz11 = __shfl_down_sync(FULL, BZ11.x, 1);
    const float nz00  = __shfl_down_sync(FULL, Z00.x, 1);
    const float nz10  = __shfl_down_sync(FULL, Z10.x, 1);
    const float nz01  = __shfl_down_sync(FULL, Z01.x, 1);
    const float nz11  = __shfl_down_sync(FULL, Z11.x, 1);

    float s_bxy = 0.f, s_bz = 0.f, s_par = 0.f, s_div = 0.f;

    // ---- element-wise losses (both k values) ----
    #pragma unroll
    for (int e = 0; e < 2; e++) {
        const float bxp = e ? BX00.y : BX00.x;
        const float byp = e ? BY00.y : BY00.x;
        const float bzp = e ? BZ00.y : BZ00.x;
        const float bxt = e ? TX.y : TX.x;
        const float byt = e ? TY.y : TY.x;
        const float bzt = e ? TZ.y : TZ.x;

        const float bxt2 = bxt*bxt, byt2 = byt*byt, bzt2 = bzt*bzt;
        const float t = bxp*bxp + byp*byp - bxt2 - byt2;
        s_bxy += __fdividef(t*t, bxt2 + byt2 + 1e-10f);
        const float d = bzp - bzt; const float d2 = d*d;
        s_bz  += __fdividef(d2*d2, bzt2 + 1e-10f);
        const float cr = bxp*byt - byp*bxt;
        s_par += __fdividef(cr*cr, bxt2 + byt2 + bzt2 + 1e-10f);
    }

    // ---- divergence loss: cell contribution from 32 corner scalars ----
    // corner naming: f_{i}{j}{k}
    const float DX = 0.1f, DY = 0.1f;
    auto cell = [&](float bx000, float bx001, float bx010, float bx011,
                    float bx100, float bx101, float bx110, float bx111,
                    float by000, float by001, float by010, float by011,
                    float by100, float by101, float by110, float by111,
                    float bz000, float bz001, float bz010, float bz011,
                    float bz100, float bz101, float bz110, float bz111,
                    float z000,  float z001,  float z010,  float z011,
                    float z100,  float z101,  float z110,  float z111)
    {
        float num =
            0.125f*DY*( (bx100+bx110+bx101+bx111)*(z101-z100+z111-z110)
                      - (bx000+bx010+bx001+bx011)*(z001-z000+z011-z010) )
          + 0.125f*DX*( (by010+by110+by011+by111)*(z011-z010+z111-z110)
                      - (by000+by100+by001+by101)*(z001-z000+z101-z100) )
          + 0.25f*DX*DY*((bz001+bz011+bz101+bz111)-(bz000+bz010+bz100+bz110))
          + (DY/6.f)*( (bx001+bx101+bx111)*(z001-z101)
                     + (bx011+bx111+bx101)*(z011-z111)
                     - (bx000+bx100+bx110)*(z000-z100)
                     - (bx010+bx110+bx100)*(z010-z110) )
          + (DX/6.f)*( (by101+by111+by011)*(z101-z111)
                     + (by001+by011+by111)*(z001-z011)
                     - (by100+by110+by010)*(z100-z110)
                     - (by000+by010+by110)*(z000-z010) );
        float bxc = 0.125f*(bx000+bx001+bx010+bx011+bx100+bx101+bx110+bx111);
        float byc = 0.125f*(by000+by001+by010+by011+by100+by101+by110+by111);
        float bzc = 0.125f*(bz000+bz001+bz010+bz011+bz100+bz101+bz110+bz111);
        float den = bxc*bxc + byc*byc + bzc*bzc + 1e-10f;
        s_div += __fdividef(num*num, den);
    };

    if (i < NI - 1 && j < NJ - 1) {            // warp-uniform branch
        // cell at k = 2*lane  (k < 63 always: max 62)
        cell(BX00.x, BX00.y, BX01.x, BX01.y, BX10.x, BX10.y, BX11.x, BX11.y,
             BY00.x, BY00.y, BY01.x, BY01.y, BY10.x, BY10.y, BY11.x, BY11.y,
             BZ00.x, BZ00.y, BZ01.x, BZ01.y, BZ10.x, BZ10.y, BZ11.x, BZ11.y,
             Z00.x,  Z00.y,  Z01.x,  Z01.y,  Z10.x,  Z10.y,  Z11.x,  Z11.y);
        // cell at k = 2*lane+1 (invalid only at lane 31 -> k=63)
        if (lane < 31) {
            cell(BX00.y, nbx00, BX01.y, nbx01, BX10.y, nbx10, BX11.y, nbx11,
                 BY00.y, nby00, BY01.y, nby01, BY10.y, nby10, BY11.y, nby11,
                 BZ00.y, nbz00, BZ01.y, nbz01, BZ10.y, nbz10, BZ11.y, nbz11,
                 Z00.y,  nz00,  Z01.y,  nz01,  Z10.y,  nz10,  Z11.y,  nz11);
        }
    }

    // ---- reduction: warp -> shared -> block -> global(double) ----
    #pragma unroll
    for (int o = 16; o; o >>= 1) {
        s_bxy += __shfl_down_sync(FULL, s_bxy, o);
        s_bz  += __shfl_down_sync(FULL, s_bz,  o);
        s_par += __shfl_down_sync(FULL, s_par, o);
        s_div += __shfl_down_sync(FULL, s_div, o);
    }
    __shared__ float sh[4][8];
    const int w = threadIdx.x >> 5;
    if (lane == 0) { sh[0][w]=s_bxy; sh[1][w]=s_bz; sh[2][w]=s_par; sh[3][w]=s_div; }
    __syncthreads();
    if (threadIdx.x < 4) {
        float s = 0.f;
        #pragma unroll
        for (int q = 0; q < 8; q++) s += sh[threadIdx.x][q];
        atomicAdd(&g_acc[threadIdx.x], (double)s);
    }
}

__global__ void finalize_kernel(float* __restrict__ out)
{
    const double N  = (double)NPIX;
    const double lb = g_acc[0] / N + g_acc[1] / N;
    const double lp = g_acc[2] / N;
    out[0] = (float)(1000.0 * lb + 1000.0 * lp);
    // loss_div = mean / DX^2 / DY^2 ; W_DIV = 100
    out[1] = (float)(100.0 * (g_acc[3] / NCELL) * 1.0e4);
}

extern "C" void kernel_launch(void* const* d_in, const int* in_sizes, int n_in,
                              void* d_out, int out_size)
{
    const float* outputs = (const float*)d_in[0];
    const float* targets = (const float*)d_in[1];
    // safety: identify by size (outputs has 3 channels, targets 4)
    if (n_in >= 2 && in_sizes[0] == 4 * NB * CVOL && in_sizes[1] == 3 * NB * CVOL) {
        const float* t = outputs; outputs = targets; targets = t;
    }
    float* out = (float*)d_out;

    init_acc_kernel<<<1, 32>>>();
    // rows = 2*256*256 = 131072 warps -> 4,194,304 threads -> 16384 blocks of 256
    loss_kernel<<<16384, 256>>>(outputs, targets);
    finalize_kernel<<<1, 1>>>(out);
}